// round 9
// baseline (speedup 1.0000x reference)
#include <cuda_runtime.h>

typedef unsigned long long ull;

#define NB 16384
#define SLONG 100
#define SSHORT 10

// ---------------- f32x2 helpers ----------------
__device__ __forceinline__ ull pk2(float lo, float hi) {
    ull r; asm("mov.b64 %0, {%1, %2};" : "=l"(r) : "f"(lo), "f"(hi)); return r;
}
__device__ __forceinline__ ull bc2(float x) {
    ull r; asm("mov.b64 %0, {%1, %1};" : "=l"(r) : "f"(x)); return r;
}
__device__ __forceinline__ void up2(ull v, float& lo, float& hi) {
    asm("mov.b64 {%0, %1}, %2;" : "=f"(lo), "=f"(hi) : "l"(v));
}
__device__ __forceinline__ ull fma2(ull a, ull b, ull c) {
    ull d; asm("fma.rn.f32x2 %0, %1, %2, %3;" : "=l"(d) : "l"(a), "l"(b), "l"(c)); return d;
}
__device__ __forceinline__ ull add2(ull a, ull b) {
    ull d; asm("add.rn.f32x2 %0, %1, %2;" : "=l"(d) : "l"(a), "l"(b)); return d;
}
__device__ __forceinline__ ull mul2(ull a, ull b) {
    ull d; asm("mul.rn.f32x2 %0, %1, %2;" : "=l"(d) : "l"(a), "l"(b)); return d;
}
__device__ __forceinline__ ull relu2(ull v) {
    float lo, hi; up2(v, lo, hi);
    return pk2(fmaxf(lo, 0.f), fmaxf(hi, 0.f));
}
__device__ __forceinline__ float ftanh(float x) {
    float xc = fminf(fmaxf(x, -12.f), 12.f);
    float e = __expf(2.f * xc);
    return __fdividef(e - 1.f, e + 1.f);
}
__device__ __forceinline__ float fsig(float x) {
    return __fdividef(1.f, 1.f + __expf(-x));
}
__device__ __forceinline__ ull tanh2(ull v) {
    float lo, hi; up2(v, lo, hi);
    return pk2(ftanh(lo), ftanh(hi));
}
__device__ __forceinline__ ull sig2(ull v) {
    float lo, hi; up2(v, lo, hi);
    return pk2(fsig(lo), fsig(hi));
}

// ---------------- device scratch ----------------
__device__ __align__(16) ull g_c1d[12 * 64];        // dup [c*3+k][oc]
__device__ __align__(16) ull g_c2v[64 * 64 * 6];    // dup [c][oc][k] k-padded to 6
__device__ __align__(16) ull g_c3v[64 * 64 * 8];    // dup [c][oc][k] k-padded to 8
__device__ ull   g_bn1scd[64], g_bn1shd[64];
__device__ ull   g_bn2scd[64], g_bn2shd[64];
__device__ ull   g_bn3scd[64], g_bn3shd[64];
__device__ float g_Wu[64];           // proj_w @ Bm  [c][i] 4x16
__device__ float g_bu[16];
__device__ ull   g_Md[16 * 64];      // dup (Cm@out_w)[j][oc]
__device__ ull   g_obd[64];
__device__ ull   g_g1d[128 * 64];
__device__ ull   g_g1bd[64];
__device__ ull   g_g2d[64 * 64];
__device__ ull   g_g2bd[64];
__device__ ull   g_h1d[64 * 32];
__device__ ull   g_h1bd[32];
__device__ ull   g_h2d[32 * 3];
__device__ float g_hf[NB * 16];

// ---------------- kernel 1: pack / fold ----------------
__global__ void precompute_kernel(
    const float* __restrict__ c1w, const float* __restrict__ c1b,
    const float* __restrict__ c2w, const float* __restrict__ c2b,
    const float* __restrict__ c3w, const float* __restrict__ c3b,
    const float* __restrict__ bn1g, const float* __restrict__ bn1b,
    const float* __restrict__ bn2g, const float* __restrict__ bn2b,
    const float* __restrict__ bn3g, const float* __restrict__ bn3b,
    const float* __restrict__ pw,  const float* __restrict__ pb,
    const float* __restrict__ Bm,  const float* __restrict__ Cm,
    const float* __restrict__ ow,  const float* __restrict__ ob,
    const float* __restrict__ g1w, const float* __restrict__ g1b,
    const float* __restrict__ g2w, const float* __restrict__ g2b,
    const float* __restrict__ h1w, const float* __restrict__ h1b,
    const float* __restrict__ h2w)
{
    int tid = blockIdx.x * blockDim.x + threadIdx.x;
    int nt  = gridDim.x * blockDim.x;
    const float S = rsqrtf(1.0f + 1e-5f);

    for (int i = tid; i < 12 * 64; i += nt) {
        int oc = i & 63, ck = i >> 6;
        g_c1d[ck * 64 + oc] = bc2(c1w[oc * 12 + ck]);
    }
    for (int i = tid; i < 64 * 64 * 6; i += nt) {    // [c][oc][k<=5]
        int k = i % 6, t = i / 6;
        int oc = t & 63, c = t >> 6;
        g_c2v[i] = (k < 5) ? bc2(c2w[oc * 320 + c * 5 + k]) : 0ull;
    }
    for (int i = tid; i < 64 * 64 * 8; i += nt) {    // [c][oc][k<=7]
        int k = i & 7, t = i >> 3;
        int oc = t & 63, c = t >> 6;
        g_c3v[i] = (k < 7) ? bc2(c3w[oc * 448 + c * 7 + k]) : 0ull;
    }
    for (int i = tid; i < 64; i += nt) {
        float s;
        s = bn1g[i] * S; g_bn1scd[i] = bc2(s); g_bn1shd[i] = bc2(fmaf(c1b[i], s, bn1b[i]));
        s = bn2g[i] * S; g_bn2scd[i] = bc2(s); g_bn2shd[i] = bc2(fmaf(c2b[i], s, bn2b[i]));
        s = bn3g[i] * S; g_bn3scd[i] = bc2(s); g_bn3shd[i] = bc2(fmaf(c3b[i], s, bn3b[i]));
        g_obd[i]  = bc2(ob[i]);
        g_g1bd[i] = bc2(g1b[i]);
        g_g2bd[i] = bc2(g2b[i]);
    }
    for (int i = tid; i < 64; i += nt) {          // W_u = proj_w(4,64) @ Bm(64,16)
        int c = i >> 4, j = i & 15;
        float s = 0.f;
        for (int h = 0; h < 64; h++) s = fmaf(pw[c * 64 + h], Bm[h * 16 + j], s);
        g_Wu[i] = s;
    }
    for (int i = tid; i < 16; i += nt) {
        float s = 0.f;
        for (int h = 0; h < 64; h++) s = fmaf(pb[h], Bm[h * 16 + i], s);
        g_bu[i] = s;
    }
    for (int i = tid; i < 16 * 64; i += nt) {     // M = Cm(16,64) @ out_w(64,64)
        int j = i >> 6, oc = i & 63;
        float s = 0.f;
        for (int c = 0; c < 64; c++) s = fmaf(Cm[j * 64 + c], ow[c * 64 + oc], s);
        g_Md[i] = bc2(s);
    }
    for (int i = tid; i < 128 * 64; i += nt) g_g1d[i] = bc2(g1w[i]);
    for (int i = tid; i < 64 * 64;  i += nt) g_g2d[i] = bc2(g2w[i]);
    for (int i = tid; i < 64 * 32;  i += nt) g_h1d[i] = bc2(h1w[i]);
    for (int i = tid; i < 32;       i += nt) g_h1bd[i] = bc2(h1b[i]);
    for (int i = tid; i < 32 * 3;   i += nt) g_h2d[i] = bc2(h2w[i]);
}

// ---------------- kernel 2: RNN scan (half-warp per batch) ----------------
__global__ __launch_bounds__(256) void rnn_kernel(
    const float* __restrict__ x, const float* __restrict__ A)
{
    __shared__ __align__(16) float sx[8][800];
    int warp = threadIdx.x >> 5, lane = threadIdx.x & 31;
    int g = lane >> 4, li = lane & 15;
    int pairBase = (blockIdx.x * 8 + warp) * 2;

    const float* src = x + (size_t)pairBase * (SLONG * 4);
    float* dst = sx[warp];
    for (int i = lane; i < 800; i += 32) dst[i] = src[i];
    __syncwarp();

    float Ar[16];
#pragma unroll
    for (int j = 0; j < 16; j++) Ar[j] = __ldg(&A[li * 16 + j]);
    float wu0 = g_Wu[li], wu1 = g_Wu[16 + li], wu2 = g_Wu[32 + li], wu3 = g_Wu[48 + li];
    float bu = g_bu[li];

    const float* xr = &sx[warp][g * 400];
    float h = 0.f;
    for (int t = 0; t < SLONG; t++) {
        float4 xv = *(const float4*)(xr + t * 4);
        float u = bu;
        u = fmaf(xv.x, wu0, u); u = fmaf(xv.y, wu1, u);
        u = fmaf(xv.z, wu2, u); u = fmaf(xv.w, wu3, u);
        float a0 = u, a1 = 0.f, a2 = 0.f, a3 = 0.f;
#pragma unroll
        for (int j = 0; j < 16; j += 4) {
            a0 = fmaf(__shfl_sync(0xffffffffu, h, j + 0, 16), Ar[j + 0], a0);
            a1 = fmaf(__shfl_sync(0xffffffffu, h, j + 1, 16), Ar[j + 1], a1);
            a2 = fmaf(__shfl_sync(0xffffffffu, h, j + 2, 16), Ar[j + 2], a2);
            a3 = fmaf(__shfl_sync(0xffffffffu, h, j + 3, 16), Ar[j + 3], a3);
        }
        h = ftanh((a0 + a1) + (a2 + a3));
    }
    g_hf[(pairBase + g) * 16 + li] = h;
}

// ---------------- kernel 3: fused conv + heads ----------------
// 1 warp = 2 batches (f32x2 lanes); lane covers oc=lane and oc=lane+32.
// Per-warp smem (ull): x 40 | act 704 (stride 11, conv1-out then conv2-out overlaid) | comb 128 | fil 64
#define OFF_X    0
#define OFF_ACT  40
#define OFF_CMB  744
#define OFF_FIL  872
#define WARP_ULL 936

__global__ __launch_bounds__(128, 3) void fused_kernel(
    const float* __restrict__ x,
    const float* __restrict__ h2b,
    float* __restrict__ out)
{
    __shared__ __align__(16) ull dsm[4 * WARP_ULL];
    int w = threadIdx.x >> 5, lane = threadIdx.x & 31;
    ull* S = dsm + w * WARP_ULL;

    int b0 = (blockIdx.x * 4 + w) * 2;
    const float* xA = x + (size_t)b0 * (SLONG * 4) + (SLONG - SSHORT) * 4;
    const float* xB = xA + SLONG * 4;
    for (int i = lane; i < 40; i += 32)
        S[OFF_X + i] = pk2(__ldg(xA + i), __ldg(xB + i));
    __syncwarp();

    ull a0[10], a1[10];
#pragma unroll
    for (int t = 0; t < 10; t++) { a0[t] = 0ull; a1[t] = 0ull; }

    // ---- conv1 (4 -> 64, k=3, pad 1) ----
#pragma unroll
    for (int c = 0; c < 4; c++) {
        ull bb[10];
#pragma unroll
        for (int t = 0; t < 10; t++) bb[t] = S[OFF_X + t * 4 + c];
#pragma unroll
        for (int k = 0; k < 3; k++) {
            ull w0 = __ldg(&g_c1d[(c * 3 + k) * 64 + lane]);
            ull w1 = __ldg(&g_c1d[(c * 3 + k) * 64 + lane + 32]);
#pragma unroll
            for (int t = 0; t < 10; t++) {
                int idx = t + k - 1;
                if (idx >= 0 && idx < 10) {
                    a0[t] = fma2(bb[idx], w0, a0[t]);
                    a1[t] = fma2(bb[idx], w1, a1[t]);
                }
            }
        }
    }
    {
        ull sc0 = g_bn1scd[lane],      sh0 = g_bn1shd[lane];
        ull sc1 = g_bn1scd[lane + 32], sh1 = g_bn1shd[lane + 32];
        ull* A0 = S + OFF_ACT + lane * 11;
        ull* A1 = S + OFF_ACT + (lane + 32) * 11;
#pragma unroll
        for (int t = 0; t < 10; t++) {
            A0[t] = relu2(fma2(a0[t], sc0, sh0));
            A1[t] = relu2(fma2(a1[t], sc1, sh1));
            a0[t] = 0ull; a1[t] = 0ull;
        }
    }
    __syncwarp();

    // ---- conv2 (64 -> 64, k=5, pad 2): k-padded LDG.128 weights ----
#pragma unroll 2
    for (int c = 0; c < 64; c++) {
        const ull* ar = S + OFF_ACT + c * 11;
        ull bb[10];
#pragma unroll
        for (int j = 0; j < 10; j++) bb[j] = ar[j];

        const ull* wp0 = g_c2v + ((size_t)c * 64 + lane) * 6;
        const ull* wp1 = wp0 + 32 * 6;
        ulonglong2 wA0 = __ldg((const ulonglong2*)wp0);        // k0,k1
        ulonglong2 wB0 = __ldg((const ulonglong2*)(wp0 + 2));  // k2,k3
        ull        w40 = __ldg(wp0 + 4);                       // k4
        ulonglong2 wA1 = __ldg((const ulonglong2*)wp1);
        ulonglong2 wB1 = __ldg((const ulonglong2*)(wp1 + 2));
        ull        w41 = __ldg(wp1 + 4);

        // k=0: t=2..9 ; k=1: t=1..9 ; k=2: t=0..9 ; k=3: t=0..8 ; k=4: t=0..7
#pragma unroll
        for (int t = 2; t < 10; t++) { a0[t] = fma2(bb[t - 2], wA0.x, a0[t]); a1[t] = fma2(bb[t - 2], wA1.x, a1[t]); }
#pragma unroll
        for (int t = 1; t < 10; t++) { a0[t] = fma2(bb[t - 1], wA0.y, a0[t]); a1[t] = fma2(bb[t - 1], wA1.y, a1[t]); }
#pragma unroll
        for (int t = 0; t < 10; t++) { a0[t] = fma2(bb[t],     wB0.x, a0[t]); a1[t] = fma2(bb[t],     wB1.x, a1[t]); }
#pragma unroll
        for (int t = 0; t < 9;  t++) { a0[t] = fma2(bb[t + 1], wB0.y, a0[t]); a1[t] = fma2(bb[t + 1], wB1.y, a1[t]); }
#pragma unroll
        for (int t = 0; t < 8;  t++) { a0[t] = fma2(bb[t + 2], w40,   a0[t]); a1[t] = fma2(bb[t + 2], w41,   a1[t]); }
    }
    {   // bn2 + relu, overlay conv2-out onto the same act region (per-warp private)
        ull sc0 = g_bn2scd[lane],      sh0 = g_bn2shd[lane];
        ull sc1 = g_bn2scd[lane + 32], sh1 = g_bn2shd[lane + 32];
        ull* B0 = S + OFF_ACT + lane * 11;
        ull* B1 = S + OFF_ACT + (lane + 32) * 11;
#pragma unroll
        for (int t = 0; t < 10; t++) {
            ull r0 = relu2(fma2(a0[t], sc0, sh0));
            ull r1 = relu2(fma2(a1[t], sc1, sh1));
            a0[t] = 0ull; a1[t] = 0ull;
            B0[t] = r0;
            B1[t] = r1;
        }
    }
    __syncwarp();

    // ---- conv3 (64 -> 64, k=7, pad 3) + mean ----
#pragma unroll 2
    for (int c = 0; c < 64; c++) {
        const ull* ar = S + OFF_ACT + c * 11;
        ull bb[10];
#pragma unroll
        for (int j = 0; j < 10; j++) bb[j] = ar[j];

        const ull* wp0 = g_c3v + (((size_t)c * 64 + lane) << 3);
        const ull* wp1 = wp0 + 32 * 8;
        ulonglong2 wA0 = __ldg((const ulonglong2*)wp0);        // k0,k1
        ulonglong2 wB0 = __ldg((const ulonglong2*)(wp0 + 2));  // k2,k3
        ulonglong2 wC0 = __ldg((const ulonglong2*)(wp0 + 4));  // k4,k5
        ull        w60 = __ldg(wp0 + 6);                       // k6
        ulonglong2 wA1 = __ldg((const ulonglong2*)wp1);
        ulonglong2 wB1 = __ldg((const ulonglong2*)(wp1 + 2));
        ulonglong2 wC1 = __ldg((const ulonglong2*)(wp1 + 4));
        ull        w61 = __ldg(wp1 + 6);

        // idx = t+k-3 in [0,9]
#pragma unroll
        for (int t = 3; t < 10; t++) { a0[t] = fma2(bb[t - 3], wA0.x, a0[t]); a1[t] = fma2(bb[t - 3], wA1.x, a1[t]); }
#pragma unroll
        for (int t = 2; t < 10; t++) { a0[t] = fma2(bb[t - 2], wA0.y, a0[t]); a1[t] = fma2(bb[t - 2], wA1.y, a1[t]); }
#pragma unroll
        for (int t = 1; t < 10; t++) { a0[t] = fma2(bb[t - 1], wB0.x, a0[t]); a1[t] = fma2(bb[t - 1], wB1.x, a1[t]); }
#pragma unroll
        for (int t = 0; t < 10; t++) { a0[t] = fma2(bb[t],     wB0.y, a0[t]); a1[t] = fma2(bb[t],     wB1.y, a1[t]); }
#pragma unroll
        for (int t = 0; t < 9;  t++) { a0[t] = fma2(bb[t + 1], wC0.x, a0[t]); a1[t] = fma2(bb[t + 1], wC1.x, a1[t]); }
#pragma unroll
        for (int t = 0; t < 8;  t++) { a0[t] = fma2(bb[t + 2], wC0.y, a0[t]); a1[t] = fma2(bb[t + 2], wC1.y, a1[t]); }
#pragma unroll
        for (int t = 0; t < 7;  t++) { a0[t] = fma2(bb[t + 3], w60,   a0[t]); a1[t] = fma2(bb[t + 3], w61,   a1[t]); }
    }
    ull sf0, sf1;
    {
        ull sc0 = g_bn3scd[lane],      sh0 = g_bn3shd[lane];
        ull sc1 = g_bn3scd[lane + 32], sh1 = g_bn3shd[lane + 32];
        ull s0 = 0ull, s1 = 0ull;
#pragma unroll
        for (int t = 0; t < 10; t++) {
            s0 = add2(s0, relu2(fma2(a0[t], sc0, sh0)));
            s1 = add2(s1, relu2(fma2(a1[t], sc1, sh1)));
        }
        ull tenth = bc2(0.1f);
        sf0 = mul2(s0, tenth);
        sf1 = mul2(s1, tenth);
        S[OFF_CMB + lane]      = sf0;
        S[OFF_CMB + lane + 32] = sf1;
    }

    // ---- long context: h_final @ M + out_b ----
    {
        const float* hA = g_hf + (size_t)b0 * 16;
        ull l0 = g_obd[lane], l1 = g_obd[lane + 32];
#pragma unroll
        for (int j = 0; j < 16; j++) {
            ull hp = pk2(__ldg(hA + j), __ldg(hA + 16 + j));
            l0 = fma2(hp, __ldg(&g_Md[j * 64 + lane]),      l0);
            l1 = fma2(hp, __ldg(&g_Md[j * 64 + lane + 32]), l1);
        }
        S[OFF_CMB + 64 + lane] = l0;
        S[OFF_CMB + 96 + lane] = l1;
    }
    __syncwarp();

    // ---- t1 = tanh(comb @ g1_w + g1_b) ----
    {
        ull t0 = g_g1bd[lane], t1v = g_g1bd[lane + 32];
#pragma unroll 8
        for (int i = 0; i < 128; i++) {
            ull cb = S[OFF_CMB + i];
            t0  = fma2(cb, __ldg(&g_g1d[i * 64 + lane]),      t0);
            t1v = fma2(cb, __ldg(&g_g1d[i * 64 + lane + 32]), t1v);
        }
        S[OFF_FIL + lane]      = tanh2(t0);
        S[OFF_FIL + lane + 32] = tanh2(t1v);
    }
    __syncwarp();

    // ---- gate = sigmoid(t1 @ g2_w + g2_b); filtered = sf * gate ----
    ull f0, f1;
    {
        ull q0 = g_g2bd[lane], q1 = g_g2bd[lane + 32];
#pragma unroll 8
        for (int i = 0; i < 64; i++) {
            ull tv = S[OFF_FIL + i];
            q0 = fma2(tv, __ldg(&g_g2d[i * 64 + lane]),      q0);
            q1 = fma2(tv, __ldg(&g_g2d[i * 64 + lane + 32]), q1);
        }
        f0 = mul2(sf0, sig2(q0));
        f1 = mul2(sf1, sig2(q1));
    }
    __syncwarp();
    S[OFF_FIL + lane]      = f0;
    S[OFF_FIL + lane + 32] = f1;
    __syncwarp();

    // ---- logits = relu(filtered @ h1_w + h1_b) @ h2_w + h2_b ----
    {
        ull acc = g_h1bd[lane];
#pragma unroll 8
        for (int i = 0; i < 64; i++)
            acc = fma2(S[OFF_FIL + i], __ldg(&g_h1d[i * 32 + lane]), acc);
        ull f = relu2(acc);
        float pl[3], ph[3];
#pragma unroll
        for (int r = 0; r < 3; r++) {
            ull p = mul2(f, g_h2d[lane * 3 + r]);
            up2(p, pl[r], ph[r]);
#pragma unroll
            for (int off = 16; off; off >>= 1) {
                pl[r] += __shfl_xor_sync(0xffffffffu, pl[r], off);
                ph[r] += __shfl_xor_sync(0xffffffffu, ph[r], off);
            }
        }
        if (lane == 0) {
#pragma unroll
            for (int r = 0; r < 3; r++) {
                float hb = __ldg(&h2b[r]);
                out[b0 * 3 + r]       = pl[r] + hb;
                out[(b0 + 1) * 3 + r] = ph[r] + hb;
            }
        }
    }
}

// ---------------- launch ----------------
extern "C" void kernel_launch(void* const* d_in, const int* in_sizes, int n_in,
                              void* d_out, int out_size)
{
    const float* x    = (const float*)d_in[0];
    const float* c1w  = (const float*)d_in[1];
    const float* c1b  = (const float*)d_in[2];
    const float* c2w  = (const float*)d_in[3];
    const float* c2b  = (const float*)d_in[4];
    const float* c3w  = (const float*)d_in[5];
    const float* c3b  = (const float*)d_in[6];
    const float* bn1g = (const float*)d_in[7];
    const float* bn1b = (const float*)d_in[8];
    const float* bn2g = (const float*)d_in[9];
    const float* bn2b = (const float*)d_in[10];
    const float* bn3g = (const float*)d_in[11];
    const float* bn3b = (const float*)d_in[12];
    const float* pw   = (const float*)d_in[13];
    const float* pb   = (const float*)d_in[14];
    const float* A    = (const float*)d_in[15];
    const float* Bm   = (const float*)d_in[16];
    const float* Cm   = (const float*)d_in[17];
    const float* ow   = (const float*)d_in[18];
    const float* ob   = (const float*)d_in[19];
    const float* g1w  = (const float*)d_in[20];
    const float* g1b  = (const float*)d_in[21];
    const float* g2w  = (const float*)d_in[22];
    const float* g2b  = (const float*)d_in[23];
    const float* h1w  = (const float*)d_in[24];
    const float* h1b  = (const float*)d_in[25];
    const float* h2w  = (const float*)d_in[26];
    const float* h2b  = (const float*)d_in[27];

    int Bn = in_sizes[0] / (SLONG * 4);   // 16384

    static int attr_set = 0;
    if (!attr_set) {
        cudaFuncSetAttribute(fused_kernel, cudaFuncAttributePreferredSharedMemoryCarveout, 100);
        attr_set = 1;
    }

    precompute_kernel<<<64, 256>>>(c1w, c1b, c2w, c2b, c3w, c3b,
                                   bn1g, bn1b, bn2g, bn2b, bn3g, bn3b,
                                   pw, pb, Bm, Cm, ow, ob,
                                   g1w, g1b, g2w, g2b, h1w, h1b, h2w);
    rnn_kernel<<<Bn / 16, 256>>>(x, A);
    fused_kernel<<<Bn / 8, 128>>>(x, h2b, (float*)d_out);
}

// round 11
// speedup vs baseline: 1.3466x; 1.3466x over previous
#include <cuda_runtime.h>

typedef unsigned long long ull;

#define NB 16384
#define SLONG 100
#define SSHORT 10

// ---------------- f32x2 helpers ----------------
__device__ __forceinline__ ull pk2(float lo, float hi) {
    ull r; asm("mov.b64 %0, {%1, %2};" : "=l"(r) : "f"(lo), "f"(hi)); return r;
}
__device__ __forceinline__ ull bc2(float x) {
    ull r; asm("mov.b64 %0, {%1, %1};" : "=l"(r) : "f"(x)); return r;
}
__device__ __forceinline__ void up2(ull v, float& lo, float& hi) {
    asm("mov.b64 {%0, %1}, %2;" : "=f"(lo), "=f"(hi) : "l"(v));
}
__device__ __forceinline__ ull fma2(ull a, ull b, ull c) {
    ull d; asm("fma.rn.f32x2 %0, %1, %2, %3;" : "=l"(d) : "l"(a), "l"(b), "l"(c)); return d;
}
__device__ __forceinline__ ull add2(ull a, ull b) {
    ull d; asm("add.rn.f32x2 %0, %1, %2;" : "=l"(d) : "l"(a), "l"(b)); return d;
}
__device__ __forceinline__ ull mul2(ull a, ull b) {
    ull d; asm("mul.rn.f32x2 %0, %1, %2;" : "=l"(d) : "l"(a), "l"(b)); return d;
}
__device__ __forceinline__ ull relu2(ull v) {
    float lo, hi; up2(v, lo, hi);
    return pk2(fmaxf(lo, 0.f), fmaxf(hi, 0.f));
}
__device__ __forceinline__ float ftanh(float x) {
    float xc = fminf(fmaxf(x, -12.f), 12.f);
    float e = __expf(2.f * xc);
    return __fdividef(e - 1.f, e + 1.f);
}
__device__ __forceinline__ float fsig(float x) {
    return __fdividef(1.f, 1.f + __expf(-x));
}
__device__ __forceinline__ ull tanh2(ull v) {
    float lo, hi; up2(v, lo, hi);
    return pk2(ftanh(lo), ftanh(hi));
}
__device__ __forceinline__ ull sig2(ull v) {
    float lo, hi; up2(v, lo, hi);
    return pk2(fsig(lo), fsig(hi));
}

// ---------------- device scratch ----------------
__device__ __align__(16) ull   g_c1d[12 * 64];       // dup [c*3+k][oc] (tiny)
__device__ __align__(16) float g_c2v[64 * 64 * 8];   // scalar [c][oc][k pad 8]
__device__ __align__(16) float g_c3v[64 * 64 * 8];   // scalar [c][oc][k pad 8]
__device__ ull   g_bn1scd[64], g_bn1shd[64];
__device__ ull   g_bn2scd[64], g_bn2shd[64];
__device__ ull   g_bn3scd[64], g_bn3shd[64];
__device__ float g_Wu[64];           // proj_w @ Bm  [c][i] 4x16
__device__ float g_bu[16];
__device__ ull   g_Md[16 * 64];      // dup (Cm@out_w)[j][oc]
__device__ ull   g_obd[64];
__device__ ull   g_g1d[128 * 64];
__device__ ull   g_g1bd[64];
__device__ ull   g_g2d[64 * 64];
__device__ ull   g_g2bd[64];
__device__ ull   g_h1d[64 * 32];
__device__ ull   g_h1bd[32];
__device__ ull   g_h2d[32 * 3];
__device__ float g_hf[NB * 16];

// ---------------- kernel 1: pack / fold ----------------
__global__ void precompute_kernel(
    const float* __restrict__ c1w, const float* __restrict__ c1b,
    const float* __restrict__ c2w, const float* __restrict__ c2b,
    const float* __restrict__ c3w, const float* __restrict__ c3b,
    const float* __restrict__ bn1g, const float* __restrict__ bn1b,
    const float* __restrict__ bn2g, const float* __restrict__ bn2b,
    const float* __restrict__ bn3g, const float* __restrict__ bn3b,
    const float* __restrict__ pw,  const float* __restrict__ pb,
    const float* __restrict__ Bm,  const float* __restrict__ Cm,
    const float* __restrict__ ow,  const float* __restrict__ ob,
    const float* __restrict__ g1w, const float* __restrict__ g1b,
    const float* __restrict__ g2w, const float* __restrict__ g2b,
    const float* __restrict__ h1w, const float* __restrict__ h1b,
    const float* __restrict__ h2w)
{
    int tid = blockIdx.x * blockDim.x + threadIdx.x;
    int nt  = gridDim.x * blockDim.x;
    const float S = rsqrtf(1.0f + 1e-5f);

    for (int i = tid; i < 12 * 64; i += nt) {
        int oc = i & 63, ck = i >> 6;
        g_c1d[ck * 64 + oc] = bc2(c1w[oc * 12 + ck]);
    }
    for (int i = tid; i < 64 * 64 * 8; i += nt) {    // [c][oc][k<5 else 0]
        int k = i & 7, t = i >> 3;
        int oc = t & 63, c = t >> 6;
        g_c2v[i] = (k < 5) ? c2w[oc * 320 + c * 5 + k] : 0.f;
    }
    for (int i = tid; i < 64 * 64 * 8; i += nt) {    // [c][oc][k<7 else 0]
        int k = i & 7, t = i >> 3;
        int oc = t & 63, c = t >> 6;
        g_c3v[i] = (k < 7) ? c3w[oc * 448 + c * 7 + k] : 0.f;
    }
    for (int i = tid; i < 64; i += nt) {
        float s;
        s = bn1g[i] * S; g_bn1scd[i] = bc2(s); g_bn1shd[i] = bc2(fmaf(c1b[i], s, bn1b[i]));
        s = bn2g[i] * S; g_bn2scd[i] = bc2(s); g_bn2shd[i] = bc2(fmaf(c2b[i], s, bn2b[i]));
        s = bn3g[i] * S; g_bn3scd[i] = bc2(s); g_bn3shd[i] = bc2(fmaf(c3b[i], s, bn3b[i]));
        g_obd[i]  = bc2(ob[i]);
        g_g1bd[i] = bc2(g1b[i]);
        g_g2bd[i] = bc2(g2b[i]);
    }
    for (int i = tid; i < 64; i += nt) {          // W_u = proj_w(4,64) @ Bm(64,16)
        int c = i >> 4, j = i & 15;
        float s = 0.f;
        for (int h = 0; h < 64; h++) s = fmaf(pw[c * 64 + h], Bm[h * 16 + j], s);
        g_Wu[i] = s;
    }
    for (int i = tid; i < 16; i += nt) {
        float s = 0.f;
        for (int h = 0; h < 64; h++) s = fmaf(pb[h], Bm[h * 16 + i], s);
        g_bu[i] = s;
    }
    for (int i = tid; i < 16 * 64; i += nt) {     // M = Cm(16,64) @ out_w(64,64)
        int j = i >> 6, oc = i & 63;
        float s = 0.f;
        for (int c = 0; c < 64; c++) s = fmaf(Cm[j * 64 + c], ow[c * 64 + oc], s);
        g_Md[i] = bc2(s);
    }
    for (int i = tid; i < 128 * 64; i += nt) g_g1d[i] = bc2(g1w[i]);
    for (int i = tid; i < 64 * 64;  i += nt) g_g2d[i] = bc2(g2w[i]);
    for (int i = tid; i < 64 * 32;  i += nt) g_h1d[i] = bc2(h1w[i]);
    for (int i = tid; i < 32;       i += nt) g_h1bd[i] = bc2(h1b[i]);
    for (int i = tid; i < 32 * 3;   i += nt) g_h2d[i] = bc2(h2w[i]);
}

// ---------------- kernel 2: RNN scan (half-warp per batch) ----------------
__global__ __launch_bounds__(256) void rnn_kernel(
    const float* __restrict__ x, const float* __restrict__ A)
{
    __shared__ __align__(16) float sx[8][800];
    int warp = threadIdx.x >> 5, lane = threadIdx.x & 31;
    int g = lane >> 4, li = lane & 15;
    int pairBase = (blockIdx.x * 8 + warp) * 2;

    const float* src = x + (size_t)pairBase * (SLONG * 4);
    float* dst = sx[warp];
    for (int i = lane; i < 800; i += 32) dst[i] = src[i];
    __syncwarp();

    float Ar[16];
#pragma unroll
    for (int j = 0; j < 16; j++) Ar[j] = __ldg(&A[li * 16 + j]);
    float wu0 = g_Wu[li], wu1 = g_Wu[16 + li], wu2 = g_Wu[32 + li], wu3 = g_Wu[48 + li];
    float bu = g_bu[li];

    const float* xr = &sx[warp][g * 400];
    float h = 0.f;
    for (int t = 0; t < SLONG; t++) {
        float4 xv = *(const float4*)(xr + t * 4);
        float u = bu;
        u = fmaf(xv.x, wu0, u); u = fmaf(xv.y, wu1, u);
        u = fmaf(xv.z, wu2, u); u = fmaf(xv.w, wu3, u);
        float a0 = u, a1 = 0.f, a2 = 0.f, a3 = 0.f;
#pragma unroll
        for (int j = 0; j < 16; j += 4) {
            a0 = fmaf(__shfl_sync(0xffffffffu, h, j + 0, 16), Ar[j + 0], a0);
            a1 = fmaf(__shfl_sync(0xffffffffu, h, j + 1, 16), Ar[j + 1], a1);
            a2 = fmaf(__shfl_sync(0xffffffffu, h, j + 2, 16), Ar[j + 2], a2);
            a3 = fmaf(__shfl_sync(0xffffffffu, h, j + 3, 16), Ar[j + 3], a3);
        }
        h = ftanh((a0 + a1) + (a2 + a3));
    }
    g_hf[(pairBase + g) * 16 + li] = h;
}

// ---------------- kernel 3: fused conv + heads ----------------
// 1 warp = 2 batches (f32x2 lanes); lane covers oc=lane and oc=lane+32.
// Per-warp smem (ull): x 40 | act 704 (stride 11, conv1-out then conv2-out overlaid) | comb 128 | fil 64
#define OFF_X    0
#define OFF_ACT  40
#define OFF_CMB  744
#define OFF_FIL  872
#define WARP_ULL 936

__global__ __launch_bounds__(128, 3) void fused_kernel(
    const float* __restrict__ x,
    const float* __restrict__ h2b,
    float* __restrict__ out)
{
    __shared__ __align__(16) ull dsm[4 * WARP_ULL];
    int w = threadIdx.x >> 5, lane = threadIdx.x & 31;
    ull* S = dsm + w * WARP_ULL;

    int b0 = (blockIdx.x * 4 + w) * 2;
    const float* xA = x + (size_t)b0 * (SLONG * 4) + (SLONG - SSHORT) * 4;
    const float* xB = xA + SLONG * 4;
    for (int i = lane; i < 40; i += 32)
        S[OFF_X + i] = pk2(__ldg(xA + i), __ldg(xB + i));
    __syncwarp();

    ull a0[10], a1[10];
#pragma unroll
    for (int t = 0; t < 10; t++) { a0[t] = 0ull; a1[t] = 0ull; }

    // ---- conv1 (4 -> 64, k=3, pad 1) ----
#pragma unroll
    for (int c = 0; c < 4; c++) {
        ull bb[10];
#pragma unroll
        for (int t = 0; t < 10; t++) bb[t] = S[OFF_X + t * 4 + c];
#pragma unroll
        for (int k = 0; k < 3; k++) {
            ull w0 = __ldg(&g_c1d[(c * 3 + k) * 64 + lane]);
            ull w1 = __ldg(&g_c1d[(c * 3 + k) * 64 + lane + 32]);
#pragma unroll
            for (int t = 0; t < 10; t++) {
                int idx = t + k - 1;
                if (idx >= 0 && idx < 10) {
                    a0[t] = fma2(bb[idx], w0, a0[t]);
                    a1[t] = fma2(bb[idx], w1, a1[t]);
                }
            }
        }
    }
    {
        ull sc0 = g_bn1scd[lane],      sh0 = g_bn1shd[lane];
        ull sc1 = g_bn1scd[lane + 32], sh1 = g_bn1shd[lane + 32];
        ull* A0 = S + OFF_ACT + lane * 11;
        ull* A1 = S + OFF_ACT + (lane + 32) * 11;
#pragma unroll
        for (int t = 0; t < 10; t++) {
            A0[t] = relu2(fma2(a0[t], sc0, sh0));
            A1[t] = relu2(fma2(a1[t], sc1, sh1));
            a0[t] = 0ull; a1[t] = 0ull;
        }
    }
    __syncwarp();

    // ---- conv2 (64 -> 64, k=5, pad 2): scalar k-padded weights, LDG.128 ----
#pragma unroll 2
    for (int c = 0; c < 64; c++) {
        const ull* ar = S + OFF_ACT + c * 11;
        ull bb[10];
#pragma unroll
        for (int j = 0; j < 10; j++) bb[j] = ar[j];

        const float* wp0 = g_c2v + (((size_t)c * 64 + lane) << 3);
        const float* wp1 = wp0 + 32 * 8;
        float4 wv0 = __ldg((const float4*)wp0);   // k0..k3
        float  w4s0 = __ldg(wp0 + 4);             // k4
        float4 wv1 = __ldg((const float4*)wp1);
        float  w4s1 = __ldg(wp1 + 4);
        ull k00 = bc2(wv0.x), k10 = bc2(wv0.y), k20 = bc2(wv0.z), k30 = bc2(wv0.w), k40 = bc2(w4s0);
        ull k01 = bc2(wv1.x), k11 = bc2(wv1.y), k21 = bc2(wv1.z), k31 = bc2(wv1.w), k41 = bc2(w4s1);

        // k=0: t=2..9 ; k=1: t=1..9 ; k=2: t=0..9 ; k=3: t=0..8 ; k=4: t=0..7
#pragma unroll
        for (int t = 2; t < 10; t++) { a0[t] = fma2(bb[t - 2], k00, a0[t]); a1[t] = fma2(bb[t - 2], k01, a1[t]); }
#pragma unroll
        for (int t = 1; t < 10; t++) { a0[t] = fma2(bb[t - 1], k10, a0[t]); a1[t] = fma2(bb[t - 1], k11, a1[t]); }
#pragma unroll
        for (int t = 0; t < 10; t++) { a0[t] = fma2(bb[t],     k20, a0[t]); a1[t] = fma2(bb[t],     k21, a1[t]); }
#pragma unroll
        for (int t = 0; t < 9;  t++) { a0[t] = fma2(bb[t + 1], k30, a0[t]); a1[t] = fma2(bb[t + 1], k31, a1[t]); }
#pragma unroll
        for (int t = 0; t < 8;  t++) { a0[t] = fma2(bb[t + 2], k40, a0[t]); a1[t] = fma2(bb[t + 2], k41, a1[t]); }
    }
    {   // bn2 + relu, overlay conv2-out onto the same act region (per-warp private)
        ull sc0 = g_bn2scd[lane],      sh0 = g_bn2shd[lane];
        ull sc1 = g_bn2scd[lane + 32], sh1 = g_bn2shd[lane + 32];
        ull* B0 = S + OFF_ACT + lane * 11;
        ull* B1 = S + OFF_ACT + (lane + 32) * 11;
#pragma unroll
        for (int t = 0; t < 10; t++) {
            ull r0 = relu2(fma2(a0[t], sc0, sh0));
            ull r1 = relu2(fma2(a1[t], sc1, sh1));
            a0[t] = 0ull; a1[t] = 0ull;
            B0[t] = r0;
            B1[t] = r1;
        }
    }
    __syncwarp();

    // ---- conv3 (64 -> 64, k=7, pad 3) + mean: scalar k-padded weights ----
#pragma unroll 2
    for (int c = 0; c < 64; c++) {
        const ull* ar = S + OFF_ACT + c * 11;
        ull bb[10];
#pragma unroll
        for (int j = 0; j < 10; j++) bb[j] = ar[j];

        const float* wp0 = g_c3v + (((size_t)c * 64 + lane) << 3);
        const float* wp1 = wp0 + 32 * 8;
        float4 wa0 = __ldg((const float4*)wp0);        // k0..k3
        float4 wb0 = __ldg((const float4*)(wp0 + 4));  // k4..k6 (+pad)
        float4 wa1 = __ldg((const float4*)wp1);
        float4 wb1 = __ldg((const float4*)(wp1 + 4));
        ull k00 = bc2(wa0.x), k10 = bc2(wa0.y), k20 = bc2(wa0.z), k30 = bc2(wa0.w);
        ull k40 = bc2(wb0.x), k50 = bc2(wb0.y), k60 = bc2(wb0.z);
        ull k01 = bc2(wa1.x), k11 = bc2(wa1.y), k21 = bc2(wa1.z), k31 = bc2(wa1.w);
        ull k41 = bc2(wb1.x), k51 = bc2(wb1.y), k61 = bc2(wb1.z);

        // idx = t+k-3 in [0,9]
#pragma unroll
        for (int t = 3; t < 10; t++) { a0[t] = fma2(bb[t - 3], k00, a0[t]); a1[t] = fma2(bb[t - 3], k01, a1[t]); }
#pragma unroll
        for (int t = 2; t < 10; t++) { a0[t] = fma2(bb[t - 2], k10, a0[t]); a1[t] = fma2(bb[t - 2], k11, a1[t]); }
#pragma unroll
        for (int t = 1; t < 10; t++) { a0[t] = fma2(bb[t - 1], k20, a0[t]); a1[t] = fma2(bb[t - 1], k21, a1[t]); }
#pragma unroll
        for (int t = 0; t < 10; t++) { a0[t] = fma2(bb[t],     k30, a0[t]); a1[t] = fma2(bb[t],     k31, a1[t]); }
#pragma unroll
        for (int t = 0; t < 9;  t++) { a0[t] = fma2(bb[t + 1], k40, a0[t]); a1[t] = fma2(bb[t + 1], k41, a1[t]); }
#pragma unroll
        for (int t = 0; t < 8;  t++) { a0[t] = fma2(bb[t + 2], k50, a0[t]); a1[t] = fma2(bb[t + 2], k51, a1[t]); }
#pragma unroll
        for (int t = 0; t < 7;  t++) { a0[t] = fma2(bb[t + 3], k60, a0[t]); a1[t] = fma2(bb[t + 3], k61, a1[t]); }
    }
    ull sf0, sf1;
    {
        ull sc0 = g_bn3scd[lane],      sh0 = g_bn3shd[lane];
        ull sc1 = g_bn3scd[lane + 32], sh1 = g_bn3shd[lane + 32];
        ull s0 = 0ull, s1 = 0ull;
#pragma unroll
        for (int t = 0; t < 10; t++) {
            s0 = add2(s0, relu2(fma2(a0[t], sc0, sh0)));
            s1 = add2(s1, relu2(fma2(a1[t], sc1, sh1)));
        }
        ull tenth = bc2(0.1f);
        sf0 = mul2(s0, tenth);
        sf1 = mul2(s1, tenth);
        S[OFF_CMB + lane]      = sf0;
        S[OFF_CMB + lane + 32] = sf1;
    }

    // ---- long context: h_final @ M + out_b ----
    {
        const float* hA = g_hf + (size_t)b0 * 16;
        ull l0 = g_obd[lane], l1 = g_obd[lane + 32];
#pragma unroll
        for (int j = 0; j < 16; j++) {
            ull hp = pk2(__ldg(hA + j), __ldg(hA + 16 + j));
            l0 = fma2(hp, __ldg(&g_Md[j * 64 + lane]),      l0);
            l1 = fma2(hp, __ldg(&g_Md[j * 64 + lane + 32]), l1);
        }
        S[OFF_CMB + 64 + lane] = l0;
        S[OFF_CMB + 96 + lane] = l1;
    }
    __syncwarp();

    // ---- t1 = tanh(comb @ g1_w + g1_b) ----
    {
        ull t0 = g_g1bd[lane], t1v = g_g1bd[lane + 32];
#pragma unroll 8
        for (int i = 0; i < 128; i++) {
            ull cb = S[OFF_CMB + i];
            t0  = fma2(cb, __ldg(&g_g1d[i * 64 + lane]),      t0);
            t1v = fma2(cb, __ldg(&g_g1d[i * 64 + lane + 32]), t1v);
        }
        S[OFF_FIL + lane]      = tanh2(t0);
        S[OFF_FIL + lane + 32] = tanh2(t1v);
    }
    __syncwarp();

    // ---- gate = sigmoid(t1 @ g2_w + g2_b); filtered = sf * gate ----
    ull f0, f1;
    {
        ull q0 = g_g2bd[lane], q1 = g_g2bd[lane + 32];
#pragma unroll 8
        for (int i = 0; i < 64; i++) {
            ull tv = S[OFF_FIL + i];
            q0 = fma2(tv, __ldg(&g_g2d[i * 64 + lane]),      q0);
            q1 = fma2(tv, __ldg(&g_g2d[i * 64 + lane + 32]), q1);
        }
        f0 = mul2(sf0, sig2(q0));
        f1 = mul2(sf1, sig2(q1));
    }
    __syncwarp();
    S[OFF_FIL + lane]      = f0;
    S[OFF_FIL + lane + 32] = f1;
    __syncwarp();

    // ---- logits = relu(filtered @ h1_w + h1_b) @ h2_w + h2_b ----
    {
        ull acc = g_h1bd[lane];
#pragma unroll 8
        for (int i = 0; i < 64; i++)
            acc = fma2(S[OFF_FIL + i], __ldg(&g_h1d[i * 32 + lane]), acc);
        ull f = relu2(acc);
        float pl[3], ph[3];
#pragma unroll
        for (int r = 0; r < 3; r++) {
            ull p = mul2(f, g_h2d[lane * 3 + r]);
            up2(p, pl[r], ph[r]);
#pragma unroll
            for (int off = 16; off; off >>= 1) {
                pl[r] += __shfl_xor_sync(0xffffffffu, pl[r], off);
                ph[r] += __shfl_xor_sync(0xffffffffu, ph[r], off);
            }
        }
        if (lane == 0) {
#pragma unroll
            for (int r = 0; r < 3; r++) {
                float hb = __ldg(&h2b[r]);
                out[b0 * 3 + r]       = pl[r] + hb;
                out[(b0 + 1) * 3 + r] = ph[r] + hb;
            }
        }
    }
}

// ---------------- launch ----------------
extern "C" void kernel_launch(void* const* d_in, const int* in_sizes, int n_in,
                              void* d_out, int out_size)
{
    const float* x    = (const float*)d_in[0];
    const float* c1w  = (const float*)d_in[1];
    const float* c1b  = (const float*)d_in[2];
    const float* c2w  = (const float*)d_in[3];
    const float* c2b  = (const float*)d_in[4];
    const float* c3w  = (const float*)d_in[5];
    const float* c3b  = (const float*)d_in[6];
    const float* bn1g = (const float*)d_in[7];
    const float* bn1b = (const float*)d_in[8];
    const float* bn2g = (const float*)d_in[9];
    const float* bn2b = (const float*)d_in[10];
    const float* bn3g = (const float*)d_in[11];
    const float* bn3b = (const float*)d_in[12];
    const float* pw   = (const float*)d_in[13];
    const float* pb   = (const float*)d_in[14];
    const float* A    = (const float*)d_in[15];
    const float* Bm   = (const float*)d_in[16];
    const float* Cm   = (const float*)d_in[17];
    const float* ow   = (const float*)d_in[18];
    const float* ob   = (const float*)d_in[19];
    const float* g1w  = (const float*)d_in[20];
    const float* g1b  = (const float*)d_in[21];
    const float* g2w  = (const float*)d_in[22];
    const float* g2b  = (const float*)d_in[23];
    const float* h1w  = (const float*)d_in[24];
    const float* h1b  = (const float*)d_in[25];
    const float* h2w  = (const float*)d_in[26];
    const float* h2b  = (const float*)d_in[27];

    int Bn = in_sizes[0] / (SLONG * 4);   // 16384

    static int attr_set = 0;
    if (!attr_set) {
        // ~114KB smem carveout (3 x 30KB blocks) leaves ~114KB L1D for the weight streams.
        cudaFuncSetAttribute(fused_kernel, cudaFuncAttributePreferredSharedMemoryCarveout, 50);
        attr_set = 1;
    }

    precompute_kernel<<<64, 256>>>(c1w, c1b, c2w, c2b, c3w, c3b,
                                   bn1g, bn1b, bn2g, bn2b, bn3g, bn3b,
                                   pw, pb, Bm, Cm, ow, ob,
                                   g1w, g1b, g2w, g2b, h1w, h1b, h2w);
    rnn_kernel<<<Bn / 16, 256>>>(x, A);
    fused_kernel<<<Bn / 8, 128>>>(x, h2b, (float*)d_out);
}

// round 12
// speedup vs baseline: 1.4416x; 1.0706x over previous
#include <cuda_runtime.h>

typedef unsigned long long ull;

#define NB 16384
#define SLONG 100
#define SSHORT 10

// ---------------- f32x2 helpers ----------------
__device__ __forceinline__ ull pk2(float lo, float hi) {
    ull r; asm("mov.b64 %0, {%1, %2};" : "=l"(r) : "f"(lo), "f"(hi)); return r;
}
__device__ __forceinline__ ull bc2(float x) {
    ull r; asm("mov.b64 %0, {%1, %1};" : "=l"(r) : "f"(x)); return r;
}
__device__ __forceinline__ void up2(ull v, float& lo, float& hi) {
    asm("mov.b64 {%0, %1}, %2;" : "=f"(lo), "=f"(hi) : "l"(v));
}
__device__ __forceinline__ ull fma2(ull a, ull b, ull c) {
    ull d; asm("fma.rn.f32x2 %0, %1, %2, %3;" : "=l"(d) : "l"(a), "l"(b), "l"(c)); return d;
}
__device__ __forceinline__ ull add2(ull a, ull b) {
    ull d; asm("add.rn.f32x2 %0, %1, %2;" : "=l"(d) : "l"(a), "l"(b)); return d;
}
__device__ __forceinline__ ull mul2(ull a, ull b) {
    ull d; asm("mul.rn.f32x2 %0, %1, %2;" : "=l"(d) : "l"(a), "l"(b)); return d;
}
__device__ __forceinline__ ull relu2(ull v) {
    float lo, hi; up2(v, lo, hi);
    return pk2(fmaxf(lo, 0.f), fmaxf(hi, 0.f));
}
__device__ __forceinline__ float ftanh(float x) {
    float xc = fminf(fmaxf(x, -12.f), 12.f);
    float e = __expf(2.f * xc);
    return __fdividef(e - 1.f, e + 1.f);
}
__device__ __forceinline__ float fsig(float x) {
    return __fdividef(1.f, 1.f + __expf(-x));
}
__device__ __forceinline__ ull tanh2(ull v) {
    float lo, hi; up2(v, lo, hi);
    return pk2(ftanh(lo), ftanh(hi));
}
__device__ __forceinline__ ull sig2(ull v) {
    float lo, hi; up2(v, lo, hi);
    return pk2(fsig(lo), fsig(hi));
}

// ---------------- device scratch ----------------
__device__ __align__(16) ull   g_c1d[12 * 64];       // dup [c*3+k][oc] (tiny)
__device__ __align__(16) float g_c2v[64 * 64 * 8];   // scalar [c][oc][k pad 8]
__device__ __align__(16) float g_c3v[64 * 64 * 8];   // scalar [c][oc][k pad 8]
__device__ ull   g_bn1scd[64], g_bn1shd[64];
__device__ ull   g_bn2scd[64], g_bn2shd[64];
__device__ ull   g_bn3scd[64], g_bn3shd[64];
__device__ float g_Wu[64];           // proj_w @ Bm  [c][i] 4x16
__device__ float g_bu[16];
__device__ ull   g_Md[16 * 64];      // dup (Cm@out_w)[j][oc]
__device__ ull   g_obd[64];
__device__ ull   g_g1d[128 * 64];
__device__ ull   g_g1bd[64];
__device__ ull   g_g2d[64 * 64];
__device__ ull   g_g2bd[64];
__device__ ull   g_h1d[64 * 32];
__device__ ull   g_h1bd[32];
__device__ ull   g_h2d[32 * 3];
__device__ float g_hf[NB * 16];

// ---------------- kernel 1: pack / fold ----------------
__global__ void precompute_kernel(
    const float* __restrict__ c1w, const float* __restrict__ c1b,
    const float* __restrict__ c2w, const float* __restrict__ c2b,
    const float* __restrict__ c3w, const float* __restrict__ c3b,
    const float* __restrict__ bn1g, const float* __restrict__ bn1b,
    const float* __restrict__ bn2g, const float* __restrict__ bn2b,
    const float* __restrict__ bn3g, const float* __restrict__ bn3b,
    const float* __restrict__ pw,  const float* __restrict__ pb,
    const float* __restrict__ Bm,  const float* __restrict__ Cm,
    const float* __restrict__ ow,  const float* __restrict__ ob,
    const float* __restrict__ g1w, const float* __restrict__ g1b,
    const float* __restrict__ g2w, const float* __restrict__ g2b,
    const float* __restrict__ h1w, const float* __restrict__ h1b,
    const float* __restrict__ h2w)
{
    int tid = blockIdx.x * blockDim.x + threadIdx.x;
    int nt  = gridDim.x * blockDim.x;
    const float S = rsqrtf(1.0f + 1e-5f);

    for (int i = tid; i < 12 * 64; i += nt) {
        int oc = i & 63, ck = i >> 6;
        g_c1d[ck * 64 + oc] = bc2(c1w[oc * 12 + ck]);
    }
    for (int i = tid; i < 64 * 64 * 8; i += nt) {    // [c][oc][k<5 else 0]
        int k = i & 7, t = i >> 3;
        int oc = t & 63, c = t >> 6;
        g_c2v[i] = (k < 5) ? c2w[oc * 320 + c * 5 + k] : 0.f;
    }
    for (int i = tid; i < 64 * 64 * 8; i += nt) {    // [c][oc][k<7 else 0]
        int k = i & 7, t = i >> 3;
        int oc = t & 63, c = t >> 6;
        g_c3v[i] = (k < 7) ? c3w[oc * 448 + c * 7 + k] : 0.f;
    }
    for (int i = tid; i < 64; i += nt) {
        float s;
        s = bn1g[i] * S; g_bn1scd[i] = bc2(s); g_bn1shd[i] = bc2(fmaf(c1b[i], s, bn1b[i]));
        s = bn2g[i] * S; g_bn2scd[i] = bc2(s); g_bn2shd[i] = bc2(fmaf(c2b[i], s, bn2b[i]));
        s = bn3g[i] * S; g_bn3scd[i] = bc2(s); g_bn3shd[i] = bc2(fmaf(c3b[i], s, bn3b[i]));
        g_obd[i]  = bc2(ob[i]);
        g_g1bd[i] = bc2(g1b[i]);
        g_g2bd[i] = bc2(g2b[i]);
    }
    for (int i = tid; i < 64; i += nt) {          // W_u = proj_w(4,64) @ Bm(64,16)
        int c = i >> 4, j = i & 15;
        float s = 0.f;
        for (int h = 0; h < 64; h++) s = fmaf(pw[c * 64 + h], Bm[h * 16 + j], s);
        g_Wu[i] = s;
    }
    for (int i = tid; i < 16; i += nt) {
        float s = 0.f;
        for (int h = 0; h < 64; h++) s = fmaf(pb[h], Bm[h * 16 + i], s);
        g_bu[i] = s;
    }
    for (int i = tid; i < 16 * 64; i += nt) {     // M = Cm(16,64) @ out_w(64,64)
        int j = i >> 6, oc = i & 63;
        float s = 0.f;
        for (int c = 0; c < 64; c++) s = fmaf(Cm[j * 64 + c], ow[c * 64 + oc], s);
        g_Md[i] = bc2(s);
    }
    for (int i = tid; i < 128 * 64; i += nt) g_g1d[i] = bc2(g1w[i]);
    for (int i = tid; i < 64 * 64;  i += nt) g_g2d[i] = bc2(g2w[i]);
    for (int i = tid; i < 64 * 32;  i += nt) g_h1d[i] = bc2(h1w[i]);
    for (int i = tid; i < 32;       i += nt) g_h1bd[i] = bc2(h1b[i]);
    for (int i = tid; i < 32 * 3;   i += nt) g_h2d[i] = bc2(h2w[i]);
}

// ---------------- kernel 2: RNN scan (half-warp per batch) ----------------
__global__ __launch_bounds__(256) void rnn_kernel(
    const float* __restrict__ x, const float* __restrict__ A)
{
    __shared__ __align__(16) float sx[8][800];
    int warp = threadIdx.x >> 5, lane = threadIdx.x & 31;
    int g = lane >> 4, li = lane & 15;
    int pairBase = (blockIdx.x * 8 + warp) * 2;

    const float* src = x + (size_t)pairBase * (SLONG * 4);
    float* dst = sx[warp];
    for (int i = lane; i < 800; i += 32) dst[i] = src[i];
    __syncwarp();

    float Ar[16];
#pragma unroll
    for (int j = 0; j < 16; j++) Ar[j] = __ldg(&A[li * 16 + j]);
    float wu0 = g_Wu[li], wu1 = g_Wu[16 + li], wu2 = g_Wu[32 + li], wu3 = g_Wu[48 + li];
    float bu = g_bu[li];

    const float* xr = &sx[warp][g * 400];
    float h = 0.f;
    for (int t = 0; t < SLONG; t++) {
        float4 xv = *(const float4*)(xr + t * 4);
        float u = bu;
        u = fmaf(xv.x, wu0, u); u = fmaf(xv.y, wu1, u);
        u = fmaf(xv.z, wu2, u); u = fmaf(xv.w, wu3, u);
        float a0 = u, a1 = 0.f, a2 = 0.f, a3 = 0.f;
#pragma unroll
        for (int j = 0; j < 16; j += 4) {
            a0 = fmaf(__shfl_sync(0xffffffffu, h, j + 0, 16), Ar[j + 0], a0);
            a1 = fmaf(__shfl_sync(0xffffffffu, h, j + 1, 16), Ar[j + 1], a1);
            a2 = fmaf(__shfl_sync(0xffffffffu, h, j + 2, 16), Ar[j + 2], a2);
            a3 = fmaf(__shfl_sync(0xffffffffu, h, j + 3, 16), Ar[j + 3], a3);
        }
        h = ftanh((a0 + a1) + (a2 + a3));
    }
    g_hf[(pairBase + g) * 16 + li] = h;
}

// ---------------- kernel 3: fused conv + heads ----------------
// 1 warp = 2 batches (f32x2 lanes); lane covers oc=lane and oc=lane+32.
// Per-warp smem (ull): x 40 | act 704 (stride 11, conv1-out then conv2-out overlaid) | comb 128 | fil 64
#define OFF_X    0
#define OFF_ACT  40
#define OFF_CMB  744
#define OFF_FIL  872
#define WARP_ULL 936

__global__ __launch_bounds__(128, 4) void fused_kernel(
    const float* __restrict__ x,
    const float* __restrict__ h2b,
    float* __restrict__ out)
{
    __shared__ __align__(16) ull dsm[4 * WARP_ULL];
    int w = threadIdx.x >> 5, lane = threadIdx.x & 31;
    ull* S = dsm + w * WARP_ULL;

    int b0 = (blockIdx.x * 4 + w) * 2;
    const float* xA = x + (size_t)b0 * (SLONG * 4) + (SLONG - SSHORT) * 4;
    const float* xB = xA + SLONG * 4;
    for (int i = lane; i < 40; i += 32)
        S[OFF_X + i] = pk2(__ldg(xA + i), __ldg(xB + i));
    __syncwarp();

    ull a0[10], a1[10];
#pragma unroll
    for (int t = 0; t < 10; t++) { a0[t] = 0ull; a1[t] = 0ull; }

    // ---- conv1 (4 -> 64, k=3, pad 1) ----
#pragma unroll
    for (int c = 0; c < 4; c++) {
        ull bb[10];
#pragma unroll
        for (int t = 0; t < 10; t++) bb[t] = S[OFF_X + t * 4 + c];
#pragma unroll
        for (int k = 0; k < 3; k++) {
            ull w0 = __ldg(&g_c1d[(c * 3 + k) * 64 + lane]);
            ull w1 = __ldg(&g_c1d[(c * 3 + k) * 64 + lane + 32]);
#pragma unroll
            for (int t = 0; t < 10; t++) {
                int idx = t + k - 1;
                if (idx >= 0 && idx < 10) {
                    a0[t] = fma2(bb[idx], w0, a0[t]);
                    a1[t] = fma2(bb[idx], w1, a1[t]);
                }
            }
        }
    }
    {
        ull sc0 = g_bn1scd[lane],      sh0 = g_bn1shd[lane];
        ull sc1 = g_bn1scd[lane + 32], sh1 = g_bn1shd[lane + 32];
        ull* A0 = S + OFF_ACT + lane * 11;
        ull* A1 = S + OFF_ACT + (lane + 32) * 11;
#pragma unroll
        for (int t = 0; t < 10; t++) {
            A0[t] = relu2(fma2(a0[t], sc0, sh0));
            A1[t] = relu2(fma2(a1[t], sc1, sh1));
            a0[t] = 0ull; a1[t] = 0ull;
        }
    }
    __syncwarp();

    // ---- conv2 (64 -> 64, k=5, pad 2): scalar k-padded weights, LDG.128 ----
    for (int c = 0; c < 64; c++) {
        const ull* ar = S + OFF_ACT + c * 11;
        ull bb[10];
#pragma unroll
        for (int j = 0; j < 10; j++) bb[j] = ar[j];

        const float* wp0 = g_c2v + (((size_t)c * 64 + lane) << 3);
        const float* wp1 = wp0 + 32 * 8;
        float4 wv0 = __ldg((const float4*)wp0);   // k0..k3
        float  w4s0 = __ldg(wp0 + 4);             // k4
        float4 wv1 = __ldg((const float4*)wp1);
        float  w4s1 = __ldg(wp1 + 4);
        ull k00 = bc2(wv0.x), k10 = bc2(wv0.y), k20 = bc2(wv0.z), k30 = bc2(wv0.w), k40 = bc2(w4s0);
        ull k01 = bc2(wv1.x), k11 = bc2(wv1.y), k21 = bc2(wv1.z), k31 = bc2(wv1.w), k41 = bc2(w4s1);

        // k=0: t=2..9 ; k=1: t=1..9 ; k=2: t=0..9 ; k=3: t=0..8 ; k=4: t=0..7
#pragma unroll
        for (int t = 2; t < 10; t++) { a0[t] = fma2(bb[t - 2], k00, a0[t]); a1[t] = fma2(bb[t - 2], k01, a1[t]); }
#pragma unroll
        for (int t = 1; t < 10; t++) { a0[t] = fma2(bb[t - 1], k10, a0[t]); a1[t] = fma2(bb[t - 1], k11, a1[t]); }
#pragma unroll
        for (int t = 0; t < 10; t++) { a0[t] = fma2(bb[t],     k20, a0[t]); a1[t] = fma2(bb[t],     k21, a1[t]); }
#pragma unroll
        for (int t = 0; t < 9;  t++) { a0[t] = fma2(bb[t + 1], k30, a0[t]); a1[t] = fma2(bb[t + 1], k31, a1[t]); }
#pragma unroll
        for (int t = 0; t < 8;  t++) { a0[t] = fma2(bb[t + 2], k40, a0[t]); a1[t] = fma2(bb[t + 2], k41, a1[t]); }
    }
    {   // bn2 + relu, overlay conv2-out onto the same act region (per-warp private)
        ull sc0 = g_bn2scd[lane],      sh0 = g_bn2shd[lane];
        ull sc1 = g_bn2scd[lane + 32], sh1 = g_bn2shd[lane + 32];
        ull* B0 = S + OFF_ACT + lane * 11;
        ull* B1 = S + OFF_ACT + (lane + 32) * 11;
#pragma unroll
        for (int t = 0; t < 10; t++) {
            ull r0 = relu2(fma2(a0[t], sc0, sh0));
            ull r1 = relu2(fma2(a1[t], sc1, sh1));
            a0[t] = 0ull; a1[t] = 0ull;
            B0[t] = r0;
            B1[t] = r1;
        }
    }
    __syncwarp();

    // ---- conv3 (64 -> 64, k=7, pad 3) + mean: scalar k-padded weights ----
    for (int c = 0; c < 64; c++) {
        const ull* ar = S + OFF_ACT + c * 11;
        ull bb[10];
#pragma unroll
        for (int j = 0; j < 10; j++) bb[j] = ar[j];

        const float* wp0 = g_c3v + (((size_t)c * 64 + lane) << 3);
        const float* wp1 = wp0 + 32 * 8;
        float4 wa0 = __ldg((const float4*)wp0);        // k0..k3
        float4 wb0 = __ldg((const float4*)(wp0 + 4));  // k4..k6 (+pad)
        float4 wa1 = __ldg((const float4*)wp1);
        float4 wb1 = __ldg((const float4*)(wp1 + 4));
        ull k00 = bc2(wa0.x), k10 = bc2(wa0.y), k20 = bc2(wa0.z), k30 = bc2(wa0.w);
        ull k40 = bc2(wb0.x), k50 = bc2(wb0.y), k60 = bc2(wb0.z);
        ull k01 = bc2(wa1.x), k11 = bc2(wa1.y), k21 = bc2(wa1.z), k31 = bc2(wa1.w);
        ull k41 = bc2(wb1.x), k51 = bc2(wb1.y), k61 = bc2(wb1.z);

        // idx = t+k-3 in [0,9]
#pragma unroll
        for (int t = 3; t < 10; t++) { a0[t] = fma2(bb[t - 3], k00, a0[t]); a1[t] = fma2(bb[t - 3], k01, a1[t]); }
#pragma unroll
        for (int t = 2; t < 10; t++) { a0[t] = fma2(bb[t - 2], k10, a0[t]); a1[t] = fma2(bb[t - 2], k11, a1[t]); }
#pragma unroll
        for (int t = 1; t < 10; t++) { a0[t] = fma2(bb[t - 1], k20, a0[t]); a1[t] = fma2(bb[t - 1], k21, a1[t]); }
#pragma unroll
        for (int t = 0; t < 10; t++) { a0[t] = fma2(bb[t],     k30, a0[t]); a1[t] = fma2(bb[t],     k31, a1[t]); }
#pragma unroll
        for (int t = 0; t < 9;  t++) { a0[t] = fma2(bb[t + 1], k40, a0[t]); a1[t] = fma2(bb[t + 1], k41, a1[t]); }
#pragma unroll
        for (int t = 0; t < 8;  t++) { a0[t] = fma2(bb[t + 2], k50, a0[t]); a1[t] = fma2(bb[t + 2], k51, a1[t]); }
#pragma unroll
        for (int t = 0; t < 7;  t++) { a0[t] = fma2(bb[t + 3], k60, a0[t]); a1[t] = fma2(bb[t + 3], k61, a1[t]); }
    }
    ull sf0, sf1;
    {
        ull sc0 = g_bn3scd[lane],      sh0 = g_bn3shd[lane];
        ull sc1 = g_bn3scd[lane + 32], sh1 = g_bn3shd[lane + 32];
        ull s0 = 0ull, s1 = 0ull;
#pragma unroll
        for (int t = 0; t < 10; t++) {
            s0 = add2(s0, relu2(fma2(a0[t], sc0, sh0)));
            s1 = add2(s1, relu2(fma2(a1[t], sc1, sh1)));
        }
        ull tenth = bc2(0.1f);
        sf0 = mul2(s0, tenth);
        sf1 = mul2(s1, tenth);
        S[OFF_CMB + lane]      = sf0;
        S[OFF_CMB + lane + 32] = sf1;
    }

    // ---- long context: h_final @ M + out_b ----
    {
        const float* hA = g_hf + (size_t)b0 * 16;
        ull l0 = g_obd[lane], l1 = g_obd[lane + 32];
#pragma unroll
        for (int j = 0; j < 16; j++) {
            ull hp = pk2(__ldg(hA + j), __ldg(hA + 16 + j));
            l0 = fma2(hp, __ldg(&g_Md[j * 64 + lane]),      l0);
            l1 = fma2(hp, __ldg(&g_Md[j * 64 + lane + 32]), l1);
        }
        S[OFF_CMB + 64 + lane] = l0;
        S[OFF_CMB + 96 + lane] = l1;
    }
    __syncwarp();

    // ---- t1 = tanh(comb @ g1_w + g1_b) ----
    {
        ull t0 = g_g1bd[lane], t1v = g_g1bd[lane + 32];
#pragma unroll 8
        for (int i = 0; i < 128; i++) {
            ull cb = S[OFF_CMB + i];
            t0  = fma2(cb, __ldg(&g_g1d[i * 64 + lane]),      t0);
            t1v = fma2(cb, __ldg(&g_g1d[i * 64 + lane + 32]), t1v);
        }
        S[OFF_FIL + lane]      = tanh2(t0);
        S[OFF_FIL + lane + 32] = tanh2(t1v);
    }
    __syncwarp();

    // ---- gate = sigmoid(t1 @ g2_w + g2_b); filtered = sf * gate ----
    ull f0, f1;
    {
        ull q0 = g_g2bd[lane], q1 = g_g2bd[lane + 32];
#pragma unroll 8
        for (int i = 0; i < 64; i++) {
            ull tv = S[OFF_FIL + i];
            q0 = fma2(tv, __ldg(&g_g2d[i * 64 + lane]),      q0);
            q1 = fma2(tv, __ldg(&g_g2d[i * 64 + lane + 32]), q1);
        }
        f0 = mul2(sf0, sig2(q0));
        f1 = mul2(sf1, sig2(q1));
    }
    __syncwarp();
    S[OFF_FIL + lane]      = f0;
    S[OFF_FIL + lane + 32] = f1;
    __syncwarp();

    // ---- logits = relu(filtered @ h1_w + h1_b) @ h2_w + h2_b ----
    {
        ull acc = g_h1bd[lane];
#pragma unroll 8
        for (int i = 0; i < 64; i++)
            acc = fma2(S[OFF_FIL + i], __ldg(&g_h1d[i * 32 + lane]), acc);
        ull f = relu2(acc);
        float pl[3], ph[3];
#pragma unroll
        for (int r = 0; r < 3; r++) {
            ull p = mul2(f, g_h2d[lane * 3 + r]);
            up2(p, pl[r], ph[r]);
#pragma unroll
            for (int off = 16; off; off >>= 1) {
                pl[r] += __shfl_xor_sync(0xffffffffu, pl[r], off);
                ph[r] += __shfl_xor_sync(0xffffffffu, ph[r], off);
            }
        }
        if (lane == 0) {
#pragma unroll
            for (int r = 0; r < 3; r++) {
                float hb = __ldg(&h2b[r]);
                out[b0 * 3 + r]       = pl[r] + hb;
                out[(b0 + 1) * 3 + r] = ph[r] + hb;
            }
        }
    }
}

// ---------------- launch ----------------
extern "C" void kernel_launch(void* const* d_in, const int* in_sizes, int n_in,
                              void* d_out, int out_size)
{
    const float* x    = (const float*)d_in[0];
    const float* c1w  = (const float*)d_in[1];
    const float* c1b  = (const float*)d_in[2];
    const float* c2w  = (const float*)d_in[3];
    const float* c2b  = (const float*)d_in[4];
    const float* c3w  = (const float*)d_in[5];
    const float* c3b  = (const float*)d_in[6];
    const float* bn1g = (const float*)d_in[7];
    const float* bn1b = (const float*)d_in[8];
    const float* bn2g = (const float*)d_in[9];
    const float* bn2b = (const float*)d_in[10];
    const float* bn3g = (const float*)d_in[11];
    const float* bn3b = (const float*)d_in[12];
    const float* pw   = (const float*)d_in[13];
    const float* pb   = (const float*)d_in[14];
    const float* A    = (const float*)d_in[15];
    const float* Bm   = (const float*)d_in[16];
    const float* Cm   = (const float*)d_in[17];
    const float* ow   = (const float*)d_in[18];
    const float* ob   = (const float*)d_in[19];
    const float* g1w  = (const float*)d_in[20];
    const float* g1b  = (const float*)d_in[21];
    const float* g2w  = (const float*)d_in[22];
    const float* g2b  = (const float*)d_in[23];
    const float* h1w  = (const float*)d_in[24];
    const float* h1b  = (const float*)d_in[25];
    const float* h2w  = (const float*)d_in[26];
    const float* h2b  = (const float*)d_in[27];

    int Bn = in_sizes[0] / (SLONG * 4);   // 16384

    static int attr_set = 0;
    if (!attr_set) {
        // 4 blocks x 30KB = 120KB smem; carveout 100 so all four fit.
        cudaFuncSetAttribute(fused_kernel, cudaFuncAttributePreferredSharedMemoryCarveout, 100);
        attr_set = 1;
    }

    precompute_kernel<<<64, 256>>>(c1w, c1b, c2w, c2b, c3w, c3b,
                                   bn1g, bn1b, bn2g, bn2b, bn3g, bn3b,
                                   pw, pb, Bm, Cm, ow, ob,
                                   g1w, g1b, g2w, g2b, h1w, h1b, h2w);
    rnn_kernel<<<Bn / 16, 256>>>(x, A);
    fused_kernel<<<Bn / 8, 128>>>(x, h2b, (float*)d_out);
}